// round 13
// baseline (speedup 1.0000x reference)
#include <cuda_runtime.h>
#include <cuda_fp16.h>
#include <math.h>
#include <stdint.h>

// Problem constants (GAT_19301583028500)
#define NN   50000      // nodes
#define EE   800000     // edges
#define IN_F 256        // in features (== H*F)
#define HH   4          // heads
#define FF   64         // per-head out features
#define SLOPE 0.2f
#define NB   ((NN + 255) / 256)   // scan blocks = 196

// ---------------- device scratch (no allocations allowed) ----------------
__device__ __half g_projh[NN * IN_F];       // [N,256] projected features, fp16 (25.6 MB)
__device__ __half g_xh   [NN * IN_F];       // x in fp16 (12.8 MB)
__device__ __half g_wt   [2 * IN_F * IN_F]; // W^T and skip^T, half, [n][k] layout
__device__ float4 g_es   [EE];              // [E,4] exp(leaky(score)) in TARGET-SORTED order
__device__ int    g_srcs [EE];              // src node per sorted edge
__device__ float4 g_ssrc [NN];              // [N,4] source scores (atomically accumulated)
__device__ float4 g_strg [NN];              // [N,4] target scores
__device__ int    g_cnt  [NN];              // per-target degree histogram
__device__ int    g_off  [NN];              // exclusive-scan offsets
__device__ int    g_fill [NN];              // scatter fill counters
__device__ int    g_bsum [256];             // scan block sums

__device__ __forceinline__ float leaky(float v) { return v > 0.f ? v : SLOPE * v; }

__device__ __forceinline__ void cp_async16(unsigned smem_addr, const void* gptr) {
    asm volatile("cp.async.cg.shared.global [%0], [%1], 16;"
                 :: "r"(smem_addr), "l"(gptr) : "memory");
}
__device__ __forceinline__ void cp_commit() { asm volatile("cp.async.commit_group;" ::: "memory"); }
template<int N_> __device__ __forceinline__ void cp_wait() {
    asm volatile("cp.async.wait_group %0;" :: "n"(N_) : "memory");
}
__device__ __forceinline__ void ldsm_x4(unsigned addr, unsigned& r0, unsigned& r1,
                                        unsigned& r2, unsigned& r3) {
    asm volatile("ldmatrix.sync.aligned.m8n8.x4.shared.b16 {%0,%1,%2,%3}, [%4];"
                 : "=r"(r0), "=r"(r1), "=r"(r2), "=r"(r3) : "r"(addr));
}
__device__ __forceinline__ void ldsm_x2(unsigned addr, unsigned& r0, unsigned& r1) {
    asm volatile("ldmatrix.sync.aligned.m8n8.x2.shared.b16 {%0,%1}, [%2];"
                 : "=r"(r0), "=r"(r1) : "r"(addr));
}
__device__ __forceinline__ float sel4(float4 v, int h) {
    float lo = (h & 1) ? v.y : v.x;
    float hi = (h & 1) ? v.w : v.z;
    return (h & 2) ? hi : lo;
}

// ---------------- sort-side init: zero histogram + fill counters ----------------
__global__ void init_sort_kernel() {
    int i = blockIdx.x * blockDim.x + threadIdx.x;
    if (i < NN) { g_cnt[i] = 0; g_fill[i] = 0; }
}

// ---------------- convert x -> fp16 (+ fold score-accumulator zeroing) ----------------
__global__ void convert_x_kernel(const float* __restrict__ x) {
    int i = blockIdx.x * blockDim.x + threadIdx.x;    // 8 floats per thread
    if (i < NN) {
        g_ssrc[i] = make_float4(0.f, 0.f, 0.f, 0.f);
        g_strg[i] = make_float4(0.f, 0.f, 0.f, 0.f);
    }
    if (i >= NN * (IN_F / 8)) return;
    const float4* xp = (const float4*)x + (long)i * 2;
    float4 v0 = xp[0], v1 = xp[1];
    __half2 h0 = __floats2half2_rn(v0.x, v0.y);
    __half2 h1 = __floats2half2_rn(v0.z, v0.w);
    __half2 h2 = __floats2half2_rn(v1.x, v1.y);
    __half2 h3 = __floats2half2_rn(v1.z, v1.w);
    uint4 o;
    o.x = *(unsigned*)&h0; o.y = *(unsigned*)&h1;
    o.z = *(unsigned*)&h2; o.w = *(unsigned*)&h3;
    *(uint4*)&g_xh[(long)i * 8] = o;
}

// ---------------- convert W, skip_w -> transposed fp16 [n][k] ----------------
__global__ void convert_w_kernel(const float* __restrict__ W, const float* __restrict__ S) {
    int i = blockIdx.x * blockDim.x + threadIdx.x;    // (m, k, n), n fastest
    if (i >= 2 * IN_F * IN_F) return;
    int m = i >> 16;
    int rem = i & 65535;
    int k = rem >> 8, n = rem & 255;
    const float* src = m ? S : W;
    g_wt[m * 65536 + n * 256 + k] = __float2half(src[k * 256 + n]);   // coalesced read
}

// ---------------- fp16 tensor-core GEMM (mma.m16n8k16, ldmatrix fragments) ----------------
// zsel=0: projh = half(xh@W)  + fused per-head score dots -> g_ssrc/g_strg
// zsel=1: out   = xh@skip_w + bias (fp32)
// CTA 128x128, BK=32, 8 warps (warp tile 64x32). Smem stride 40 halves (conflict-free).
#define HS 40

__global__ __launch_bounds__(256) void gemm_fp16(float* __restrict__ out,
                                                 const float* __restrict__ bias,
                                                 const float* __restrict__ a_src,
                                                 const float* __restrict__ a_trg,
                                                 int M, int zsel) {
    __shared__ __half As [2][128 * HS];
    __shared__ __half BsT[2][128 * HS];

    const __half* Ah = g_xh;
    const __half* Bt = g_wt + zsel * 65536;

    const int NC = 256;
    const int tid  = threadIdx.x;
    const int wid  = tid >> 5;
    const int lane = tid & 31;
    const int gid  = lane >> 2;
    const int tig  = lane & 3;
    const int warp_m = wid & 1;
    const int warp_n = wid >> 1;

    const int rowBase = blockIdx.x * 128;
    const int colBase = blockIdx.y * 128;

    float acc[4][4][4];
    #pragma unroll
    for (int i = 0; i < 4; i++)
        #pragma unroll
        for (int j = 0; j < 4; j++)
            #pragma unroll
            for (int q = 0; q < 4; q++) acc[i][j][q] = 0.f;

    unsigned sA[2], sB[2];
    sA[0] = (unsigned)__cvta_generic_to_shared(&As[0][0]);
    sA[1] = (unsigned)__cvta_generic_to_shared(&As[1][0]);
    sB[0] = (unsigned)__cvta_generic_to_shared(&BsT[0][0]);
    sB[1] = (unsigned)__cvta_generic_to_shared(&BsT[1][0]);

    const unsigned laneAoff = ((lane & 15) * HS + ((lane >> 4) << 3)) * 2;
    const unsigned laneBoff = ((lane & 7) * HS + (((lane >> 3) & 1) << 3)) * 2;

    auto prefetch = [&](int kt, int buf) {
        #pragma unroll
        for (int it = 0; it < 2; it++) {
            int c = tid + it * 256;
            int r = c >> 2, seg = c & 3;
            int grow = min(rowBase + r, M - 1);
            cp_async16(sA[buf] + (r * HS + seg * 8) * 2,
                       &Ah[(long)grow * 256 + kt * 32 + seg * 8]);
            cp_async16(sB[buf] + (r * HS + seg * 8) * 2,
                       &Bt[(long)(colBase + r) * 256 + kt * 32 + seg * 8]);
        }
    };

    prefetch(0, 0);
    cp_commit();

    const int KT = 8;    // 256/32
    for (int kt = 0; kt < KT; kt++) {
        int buf = kt & 1;
        if (kt + 1 < KT) {
            prefetch(kt + 1, buf ^ 1);
            cp_commit();
            cp_wait<1>();
        } else {
            cp_wait<0>();
        }
        __syncthreads();

        #pragma unroll
        for (int ks = 0; ks < 2; ks++) {
            unsigned af[4][4];
            #pragma unroll
            for (int mt = 0; mt < 4; mt++)
                ldsm_x4(sA[buf] + laneAoff + ((warp_m * 64 + mt * 16) * HS + ks * 16) * 2,
                        af[mt][0], af[mt][1], af[mt][2], af[mt][3]);
            unsigned bf[4][2];
            #pragma unroll
            for (int nt = 0; nt < 4; nt++)
                ldsm_x2(sB[buf] + laneBoff + ((warp_n * 32 + nt * 8) * HS + ks * 16) * 2,
                        bf[nt][0], bf[nt][1]);
            #pragma unroll
            for (int mt = 0; mt < 4; mt++)
                #pragma unroll
                for (int nt = 0; nt < 4; nt++) {
                    asm volatile(
                        "mma.sync.aligned.m16n8k16.row.col.f32.f16.f16.f32 "
                        "{%0,%1,%2,%3}, {%4,%5,%6,%7}, {%8,%9}, {%0,%1,%2,%3};"
                        : "+f"(acc[mt][nt][0]), "+f"(acc[mt][nt][1]),
                          "+f"(acc[mt][nt][2]), "+f"(acc[mt][nt][3])
                        : "r"(af[mt][0]), "r"(af[mt][1]), "r"(af[mt][2]), "r"(af[mt][3]),
                          "r"(bf[nt][0]), "r"(bf[nt][1]));
                }
        }
        __syncthreads();
    }

    if (zsel == 0) {
        // ---- epilogue A: fused score partial dots -> atomic add ----
        const int head = blockIdx.y * 2 + (warp_n >> 1);
        const float* Ahd = a_src + head * 64;
        const float* Thd = a_trg + head * 64;
        float avs[4][2], avt[4][2];
        #pragma unroll
        for (int nt = 0; nt < 4; nt++) {
            int f = (warp_n & 1) * 32 + nt * 8 + 2 * tig;
            avs[nt][0] = Ahd[f]; avs[nt][1] = Ahd[f + 1];
            avt[nt][0] = Thd[f]; avt[nt][1] = Thd[f + 1];
        }
        float* S = (float*)g_ssrc;
        float* T = (float*)g_strg;
        #pragma unroll
        for (int mt = 0; mt < 4; mt++) {
            float s0 = 0.f, s1 = 0.f, t0 = 0.f, t1 = 0.f;
            #pragma unroll
            for (int nt = 0; nt < 4; nt++) {
                s0 += acc[mt][nt][0] * avs[nt][0] + acc[mt][nt][1] * avs[nt][1];
                s1 += acc[mt][nt][2] * avs[nt][0] + acc[mt][nt][3] * avs[nt][1];
                t0 += acc[mt][nt][0] * avt[nt][0] + acc[mt][nt][1] * avt[nt][1];
                t1 += acc[mt][nt][2] * avt[nt][0] + acc[mt][nt][3] * avt[nt][1];
            }
            #pragma unroll
            for (int o = 1; o < 4; o <<= 1) {
                s0 += __shfl_xor_sync(0xffffffffu, s0, o);
                s1 += __shfl_xor_sync(0xffffffffu, s1, o);
                t0 += __shfl_xor_sync(0xffffffffu, t0, o);
                t1 += __shfl_xor_sync(0xffffffffu, t1, o);
            }
            if (tig == 0) {
                int r0 = rowBase + warp_m * 64 + mt * 16 + gid;
                int r1 = r0 + 8;
                if (r0 < M) { atomicAdd(&S[r0 * 4 + head], s0); atomicAdd(&T[r0 * 4 + head], t0); }
                if (r1 < M) { atomicAdd(&S[r1 * 4 + head], s1); atomicAdd(&T[r1 * 4 + head], t1); }
            }
        }
        // ---- epilogue B: store fp16 proj ----
        #pragma unroll
        for (int mt = 0; mt < 4; mt++) {
            int r0 = rowBase + warp_m * 64 + mt * 16 + gid;
            int r1 = r0 + 8;
            #pragma unroll
            for (int nt = 0; nt < 4; nt++) {
                int col = colBase + warp_n * 32 + nt * 8 + 2 * tig;
                if (r0 < M)
                    *(__half2*)&g_projh[(long)r0 * NC + col] =
                        __floats2half2_rn(acc[mt][nt][0], acc[mt][nt][1]);
                if (r1 < M)
                    *(__half2*)&g_projh[(long)r1 * NC + col] =
                        __floats2half2_rn(acc[mt][nt][2], acc[mt][nt][3]);
            }
        }
    } else {
        // ---- epilogue: fp32 out = skip projection + bias ----
        #pragma unroll
        for (int mt = 0; mt < 4; mt++) {
            int r0 = rowBase + warp_m * 64 + mt * 16 + gid;
            int r1 = r0 + 8;
            #pragma unroll
            for (int nt = 0; nt < 4; nt++) {
                int col = colBase + warp_n * 32 + nt * 8 + 2 * tig;
                float b0 = bias[col], b1 = bias[col + 1];
                if (r0 < M) {
                    float2 v = make_float2(acc[mt][nt][0] + b0, acc[mt][nt][1] + b1);
                    *(float2*)&out[(long)r0 * NC + col] = v;
                }
                if (r1 < M) {
                    float2 v = make_float2(acc[mt][nt][2] + b0, acc[mt][nt][3] + b1);
                    *(float2*)&out[(long)r1 * NC + col] = v;
                }
            }
        }
    }
}

// ---------------- counting sort: histogram ----------------
__global__ void hist_kernel(const int* __restrict__ etrg) {
    int e = blockIdx.x * blockDim.x + threadIdx.x;
    if (e < EE) atomicAdd(&g_cnt[etrg[e]], 1);
}

// ---------------- scan step 1: per-block exclusive scan + block sums ----------------
__global__ void scan1_kernel() {
    __shared__ int s[256];
    int tid = threadIdx.x;
    int gi = blockIdx.x * 256 + tid;
    int v = (gi < NN) ? g_cnt[gi] : 0;
    s[tid] = v;
    __syncthreads();
    #pragma unroll
    for (int o = 1; o < 256; o <<= 1) {
        int t = (tid >= o) ? s[tid - o] : 0;
        __syncthreads();
        s[tid] += t;
        __syncthreads();
    }
    if (gi < NN) g_off[gi] = s[tid] - v;
    if (tid == 255) g_bsum[blockIdx.x] = s[255];
}

// ---------------- scan steps 2+3 fused ----------------
__global__ void scan23_kernel() {
    __shared__ int s[256];
    int tid = threadIdx.x;
    int v = (tid < NB) ? g_bsum[tid] : 0;
    s[tid] = v;
    __syncthreads();
    #pragma unroll
    for (int o = 1; o < 256; o <<= 1) {
        int t = (tid >= o) ? s[tid - o] : 0;
        __syncthreads();
        s[tid] += t;
        __syncthreads();
    }
    int myoff = (blockIdx.x == 0) ? 0 : s[blockIdx.x - 1];
    int gi = blockIdx.x * 256 + tid;
    if (gi < NN) g_off[gi] += myoff;
}

// ---------------- fused scatter: compute exp(leaky(score)), write sorted ----------------
__global__ void scatter_kernel(const int* __restrict__ esrc, const int* __restrict__ etrg) {
    int e = blockIdx.x * blockDim.x + threadIdx.x;
    if (e >= EE) return;
    int s = esrc[e], t = etrg[e];
    float4 ss = g_ssrc[s];
    float4 st = g_strg[t];
    float4 v;
    v.x = expf(leaky(ss.x + st.x));
    v.y = expf(leaky(ss.y + st.y));
    v.z = expf(leaky(ss.z + st.z));
    v.w = expf(leaky(ss.w + st.w));
    int idx = g_off[t] + atomicAdd(&g_fill[t], 1);
    g_es[idx] = v;
    g_srcs[idx] = s;
}

// ---------------- aggregation: warp per target, MLP-4 pipelined fp16 gather ----------------
__global__ __launch_bounds__(256) void aggregate_kernel(float* __restrict__ out) {
    int w = (blockIdx.x * blockDim.x + threadIdx.x) >> 5;
    if (w >= NN) return;
    int lane = threadIdx.x & 31;
    int base = g_off[w];
    int deg  = g_cnt[w];
    const int head = lane >> 3;            // 8 cols per lane -> one head

    float dsum = 0.f;                      // this head's softmax denominator
    float2 acc0 = make_float2(0.f, 0.f), acc1 = acc0, acc2 = acc0, acc3 = acc0;
    const __half* ph = g_projh + (long)lane * 8;

    // main loop: batches of 4 -> 4 independent in-flight gathers (MLP ~4)
    int degm = deg & ~3;
    for (int i0 = 0; i0 < degm; i0 += 4) {
        float aa[4];
        uint4 hh[4];
        #pragma unroll
        for (int j = 0; j < 4; j++) {
            float4 ex = g_es[base + i0 + j];   // uniform -> broadcast
            int s = g_srcs[base + i0 + j];
            aa[j] = sel4(ex, head);
            hh[j] = *(const uint4*)(ph + (long)s * 256);
        }
        #pragma unroll
        for (int j = 0; j < 4; j++) {
            float a = aa[j];
            dsum += a;
            float2 f0 = __half22float2(*(__half2*)&hh[j].x);
            float2 f1 = __half22float2(*(__half2*)&hh[j].y);
            float2 f2 = __half22float2(*(__half2*)&hh[j].z);
            float2 f3 = __half22float2(*(__half2*)&hh[j].w);
            acc0.x += f0.x * a; acc0.y += f0.y * a;
            acc1.x += f1.x * a; acc1.y += f1.y * a;
            acc2.x += f2.x * a; acc2.y += f2.y * a;
            acc3.x += f3.x * a; acc3.y += f3.y * a;
        }
    }
    // tail
    for (int i = degm; i < deg; i++) {
        float4 ex = g_es[base + i];
        int s = g_srcs[base + i];
        float a = sel4(ex, head);
        dsum += a;
        uint4 h = *(const uint4*)(ph + (long)s * 256);
        float2 f0 = __half22float2(*(__half2*)&h.x);
        float2 f1 = __half22float2(*(__half2*)&h.y);
        float2 f2 = __half22float2(*(__half2*)&h.z);
        float2 f3 = __half22float2(*(__half2*)&h.w);
        acc0.x += f0.x * a; acc0.y += f0.y * a;
        acc1.x += f1.x * a; acc1.y += f1.y * a;
        acc2.x += f2.x * a; acc2.y += f2.y * a;
        acc3.x += f3.x * a; acc3.y += f3.y * a;
    }
    float invh = 1.f / (dsum + 1e-16f);

    float* orow = out + (long)w * 256 + lane * 8;
    float4 v0 = *(float4*)orow;
    float4 v1 = *(float4*)(orow + 4);
    v0.x = leaky(v0.x + acc0.x * invh); v0.y = leaky(v0.y + acc0.y * invh);
    v0.z = leaky(v0.z + acc1.x * invh); v0.w = leaky(v0.w + acc1.y * invh);
    v1.x = leaky(v1.x + acc2.x * invh); v1.y = leaky(v1.y + acc2.y * invh);
    v1.z = leaky(v1.z + acc3.x * invh); v1.w = leaky(v1.w + acc3.y * invh);
    *(float4*)orow       = v0;
    *(float4*)(orow + 4) = v1;
}

// ---------------- launch: fork-join stream DAG (graph-capturable) ----------------
extern "C" void kernel_launch(void* const* d_in, const int* in_sizes, int n_in,
                              void* d_out, int out_size) {
    const float* x      = (const float*)d_in[0];
    const float* W      = (const float*)d_in[1];
    const float* a_src  = (const float*)d_in[2];
    const float* a_trg  = (const float*)d_in[3];
    const float* skip_w = (const float*)d_in[4];
    const float* bias   = (const float*)d_in[5];
    const int*   esrc   = (const int*)d_in[6];
    const int*   etrg   = (const int*)d_in[7];
    float* out = (float*)d_out;

    // one-time infra (created on the uncaptured correctness call; reused under capture)
    static cudaStream_t sSort = nullptr, sScat = nullptr;
    static cudaEvent_t evFork = nullptr, evSort = nullptr, evZ0 = nullptr, evScat = nullptr;
    if (!sSort) {
        cudaStreamCreateWithFlags(&sSort, cudaStreamNonBlocking);
        cudaStreamCreateWithFlags(&sScat, cudaStreamNonBlocking);
        cudaEventCreateWithFlags(&evFork, cudaEventDisableTiming);
        cudaEventCreateWithFlags(&evSort, cudaEventDisableTiming);
        cudaEventCreateWithFlags(&evZ0,   cudaEventDisableTiming);
        cudaEventCreateWithFlags(&evScat, cudaEventDisableTiming);
    }

    // ---- fork: sort chain on sSort, concurrent with converts+GEMMs ----
    cudaEventRecord(evFork, 0);
    cudaStreamWaitEvent(sSort, evFork, 0);
    init_sort_kernel<<<(NN + 255) / 256, 256, 0, sSort>>>();
    hist_kernel<<<(EE + 255) / 256, 256, 0, sSort>>>(etrg);
    scan1_kernel<<<NB, 256, 0, sSort>>>();
    scan23_kernel<<<NB, 256, 0, sSort>>>();
    cudaEventRecord(evSort, sSort);

    // ---- main: converts, then proj GEMM (z=0, fused scores) ----
    convert_x_kernel<<<(NN * 32 + 255) / 256, 256>>>(x);
    convert_w_kernel<<<(2 * IN_F * IN_F + 255) / 256, 256>>>(W, skip_w);
    dim3 ggrid((NN + 127) / 128, 2);
    gemm_fp16<<<ggrid, 256>>>(out, bias, a_src, a_trg, NN, 0);
    cudaEventRecord(evZ0, 0);

    // ---- scatter on sScat (needs scores + sort), concurrent with skip GEMM ----
    cudaStreamWaitEvent(sScat, evZ0, 0);
    cudaStreamWaitEvent(sScat, evSort, 0);
    scatter_kernel<<<(EE + 255) / 256, 256, 0, sScat>>>(esrc, etrg);
    cudaEventRecord(evScat, sScat);

    // ---- main: skip GEMM (z=1) concurrent with scatter ----
    gemm_fp16<<<ggrid, 256>>>(out, bias, a_src, a_trg, NN, 1);

    // ---- join, then aggregate ----
    cudaStreamWaitEvent(0, evScat, 0);
    aggregate_kernel<<<(NN * 32 + 255) / 256, 256>>>(out);
}

// round 14
// speedup vs baseline: 1.0551x; 1.0551x over previous
#include <cuda_runtime.h>
#include <cuda_fp16.h>
#include <math.h>
#include <stdint.h>

// Problem constants (GAT_19301583028500)
#define NN   50000      // nodes
#define EE   800000     // edges
#define IN_F 256        // in features (== H*F)
#define HH   4          // heads
#define FF   64         // per-head out features
#define SLOPE 0.2f
#define NB   ((NN + 255) / 256)   // scan blocks = 196

// ---------------- device scratch (no allocations allowed) ----------------
__device__ __half g_projh[NN * IN_F];       // [N,256] projected features, fp16 (25.6 MB)
__device__ __half g_xh   [NN * IN_F];       // x in fp16 (12.8 MB)
__device__ __half g_wt   [2 * IN_F * IN_F]; // W^T and skip^T, half, [n][k] layout
__device__ float4 g_es   [EE];              // [E,4] exp(leaky(score)) in TARGET-SORTED order
__device__ int    g_srcs [EE];              // src node per sorted edge
__device__ float4 g_ssrc [NN];              // [N,4] source scores (atomically accumulated)
__device__ float4 g_strg [NN];              // [N,4] target scores
__device__ int    g_cnt  [NN];              // per-target degree histogram
__device__ int    g_off  [NN];              // exclusive-scan offsets
__device__ int    g_fill [NN];              // scatter fill counters
__device__ int    g_bsum [256];             // scan block sums

__device__ __forceinline__ float leaky(float v) { return v > 0.f ? v : SLOPE * v; }

__device__ __forceinline__ void cp_async16(unsigned smem_addr, const void* gptr) {
    asm volatile("cp.async.cg.shared.global [%0], [%1], 16;"
                 :: "r"(smem_addr), "l"(gptr) : "memory");
}
__device__ __forceinline__ void cp_commit() { asm volatile("cp.async.commit_group;" ::: "memory"); }
template<int N_> __device__ __forceinline__ void cp_wait() {
    asm volatile("cp.async.wait_group %0;" :: "n"(N_) : "memory");
}
__device__ __forceinline__ void ldsm_x4(unsigned addr, unsigned& r0, unsigned& r1,
                                        unsigned& r2, unsigned& r3) {
    asm volatile("ldmatrix.sync.aligned.m8n8.x4.shared.b16 {%0,%1,%2,%3}, [%4];"
                 : "=r"(r0), "=r"(r1), "=r"(r2), "=r"(r3) : "r"(addr));
}
__device__ __forceinline__ void ldsm_x2(unsigned addr, unsigned& r0, unsigned& r1) {
    asm volatile("ldmatrix.sync.aligned.m8n8.x2.shared.b16 {%0,%1}, [%2];"
                 : "=r"(r0), "=r"(r1) : "r"(addr));
}
__device__ __forceinline__ float sel4(float4 v, int h) {
    float lo = (h & 1) ? v.y : v.x;
    float hi = (h & 1) ? v.w : v.z;
    return (h & 2) ? hi : lo;
}

// ---------------- sort-side init: zero histogram + fill counters ----------------
__global__ void init_sort_kernel() {
    int i = blockIdx.x * blockDim.x + threadIdx.x;
    if (i < NN) { g_cnt[i] = 0; g_fill[i] = 0; }
}

// ---------------- merged conversions: x -> fp16, W/skip -> transposed fp16 [n][k],
//                  + fold score-accumulator zeroing ----------------
__global__ void convert_kernel(const float* __restrict__ x, const float* __restrict__ W,
                               const float* __restrict__ S) {
    long i = (long)blockIdx.x * blockDim.x + threadIdx.x;
    if (i < NN) {
        g_ssrc[i] = make_float4(0.f, 0.f, 0.f, 0.f);
        g_strg[i] = make_float4(0.f, 0.f, 0.f, 0.f);
    }
    if (i < (long)NN * 32) {               // x: 8 floats per thread
        const float4* xp = (const float4*)x + i * 2;
        float4 v0 = xp[0], v1 = xp[1];
        __half2 h0 = __floats2half2_rn(v0.x, v0.y);
        __half2 h1 = __floats2half2_rn(v0.z, v0.w);
        __half2 h2 = __floats2half2_rn(v1.x, v1.y);
        __half2 h3 = __floats2half2_rn(v1.z, v1.w);
        uint4 o;
        o.x = *(unsigned*)&h0; o.y = *(unsigned*)&h1;
        o.z = *(unsigned*)&h2; o.w = *(unsigned*)&h3;
        *(uint4*)&g_xh[i * 8] = o;
        return;
    }
    long j = i - (long)NN * 32;            // weights: transpose to [n][k]
    if (j >= 2 * 65536) return;
    int m = (int)(j >> 16);
    int rem = (int)(j & 65535);
    int k = rem >> 8, n = rem & 255;
    const float* src = m ? S : W;
    g_wt[m * 65536 + n * 256 + k] = __float2half(src[k * 256 + n]);   // coalesced read
}

// ---------------- fp16 tensor-core GEMM (mma.m16n8k16, ldmatrix fragments) ----------------
// zsel=0: projh = half(xh@W)  + fused per-head score dots -> g_ssrc/g_strg
// zsel=1: out   = xh@skip_w + bias (fp32)
// CTA 128x128, BK=32, 8 warps (warp tile 64x32). Smem stride 40 halves (conflict-free).
#define HS 40

__global__ __launch_bounds__(256) void gemm_fp16(float* __restrict__ out,
                                                 const float* __restrict__ bias,
                                                 const float* __restrict__ a_src,
                                                 const float* __restrict__ a_trg,
                                                 int M, int zsel) {
    __shared__ __half As [2][128 * HS];
    __shared__ __half BsT[2][128 * HS];

    const __half* Ah = g_xh;
    const __half* Bt = g_wt + zsel * 65536;

    const int NC = 256;
    const int tid  = threadIdx.x;
    const int wid  = tid >> 5;
    const int lane = tid & 31;
    const int gid  = lane >> 2;
    const int tig  = lane & 3;
    const int warp_m = wid & 1;
    const int warp_n = wid >> 1;

    const int rowBase = blockIdx.x * 128;
    const int colBase = blockIdx.y * 128;

    float acc[4][4][4];
    #pragma unroll
    for (int i = 0; i < 4; i++)
        #pragma unroll
        for (int j = 0; j < 4; j++)
            #pragma unroll
            for (int q = 0; q < 4; q++) acc[i][j][q] = 0.f;

    unsigned sA[2], sB[2];
    sA[0] = (unsigned)__cvta_generic_to_shared(&As[0][0]);
    sA[1] = (unsigned)__cvta_generic_to_shared(&As[1][0]);
    sB[0] = (unsigned)__cvta_generic_to_shared(&BsT[0][0]);
    sB[1] = (unsigned)__cvta_generic_to_shared(&BsT[1][0]);

    const unsigned laneAoff = ((lane & 15) * HS + ((lane >> 4) << 3)) * 2;
    const unsigned laneBoff = ((lane & 7) * HS + (((lane >> 3) & 1) << 3)) * 2;

    auto prefetch = [&](int kt, int buf) {
        #pragma unroll
        for (int it = 0; it < 2; it++) {
            int c = tid + it * 256;
            int r = c >> 2, seg = c & 3;
            int grow = min(rowBase + r, M - 1);
            cp_async16(sA[buf] + (r * HS + seg * 8) * 2,
                       &Ah[(long)grow * 256 + kt * 32 + seg * 8]);
            cp_async16(sB[buf] + (r * HS + seg * 8) * 2,
                       &Bt[(long)(colBase + r) * 256 + kt * 32 + seg * 8]);
        }
    };

    prefetch(0, 0);
    cp_commit();

    const int KT = 8;    // 256/32
    for (int kt = 0; kt < KT; kt++) {
        int buf = kt & 1;
        if (kt + 1 < KT) {
            prefetch(kt + 1, buf ^ 1);
            cp_commit();
            cp_wait<1>();
        } else {
            cp_wait<0>();
        }
        __syncthreads();

        #pragma unroll
        for (int ks = 0; ks < 2; ks++) {
            unsigned af[4][4];
            #pragma unroll
            for (int mt = 0; mt < 4; mt++)
                ldsm_x4(sA[buf] + laneAoff + ((warp_m * 64 + mt * 16) * HS + ks * 16) * 2,
                        af[mt][0], af[mt][1], af[mt][2], af[mt][3]);
            unsigned bf[4][2];
            #pragma unroll
            for (int nt = 0; nt < 4; nt++)
                ldsm_x2(sB[buf] + laneBoff + ((warp_n * 32 + nt * 8) * HS + ks * 16) * 2,
                        bf[nt][0], bf[nt][1]);
            #pragma unroll
            for (int mt = 0; mt < 4; mt++)
                #pragma unroll
                for (int nt = 0; nt < 4; nt++) {
                    asm volatile(
                        "mma.sync.aligned.m16n8k16.row.col.f32.f16.f16.f32 "
                        "{%0,%1,%2,%3}, {%4,%5,%6,%7}, {%8,%9}, {%0,%1,%2,%3};"
                        : "+f"(acc[mt][nt][0]), "+f"(acc[mt][nt][1]),
                          "+f"(acc[mt][nt][2]), "+f"(acc[mt][nt][3])
                        : "r"(af[mt][0]), "r"(af[mt][1]), "r"(af[mt][2]), "r"(af[mt][3]),
                          "r"(bf[nt][0]), "r"(bf[nt][1]));
                }
        }
        __syncthreads();
    }

    if (zsel == 0) {
        // ---- epilogue A: fused score partial dots -> atomic add ----
        const int head = blockIdx.y * 2 + (warp_n >> 1);
        const float* Ahd = a_src + head * 64;
        const float* Thd = a_trg + head * 64;
        float avs[4][2], avt[4][2];
        #pragma unroll
        for (int nt = 0; nt < 4; nt++) {
            int f = (warp_n & 1) * 32 + nt * 8 + 2 * tig;
            avs[nt][0] = Ahd[f]; avs[nt][1] = Ahd[f + 1];
            avt[nt][0] = Thd[f]; avt[nt][1] = Thd[f + 1];
        }
        float* S = (float*)g_ssrc;
        float* T = (float*)g_strg;
        #pragma unroll
        for (int mt = 0; mt < 4; mt++) {
            float s0 = 0.f, s1 = 0.f, t0 = 0.f, t1 = 0.f;
            #pragma unroll
            for (int nt = 0; nt < 4; nt++) {
                s0 += acc[mt][nt][0] * avs[nt][0] + acc[mt][nt][1] * avs[nt][1];
                s1 += acc[mt][nt][2] * avs[nt][0] + acc[mt][nt][3] * avs[nt][1];
                t0 += acc[mt][nt][0] * avt[nt][0] + acc[mt][nt][1] * avt[nt][1];
                t1 += acc[mt][nt][2] * avt[nt][0] + acc[mt][nt][3] * avt[nt][1];
            }
            #pragma unroll
            for (int o = 1; o < 4; o <<= 1) {
                s0 += __shfl_xor_sync(0xffffffffu, s0, o);
                s1 += __shfl_xor_sync(0xffffffffu, s1, o);
                t0 += __shfl_xor_sync(0xffffffffu, t0, o);
                t1 += __shfl_xor_sync(0xffffffffu, t1, o);
            }
            if (tig == 0) {
                int r0 = rowBase + warp_m * 64 + mt * 16 + gid;
                int r1 = r0 + 8;
                if (r0 < M) { atomicAdd(&S[r0 * 4 + head], s0); atomicAdd(&T[r0 * 4 + head], t0); }
                if (r1 < M) { atomicAdd(&S[r1 * 4 + head], s1); atomicAdd(&T[r1 * 4 + head], t1); }
            }
        }
        // ---- epilogue B: store fp16 proj ----
        #pragma unroll
        for (int mt = 0; mt < 4; mt++) {
            int r0 = rowBase + warp_m * 64 + mt * 16 + gid;
            int r1 = r0 + 8;
            #pragma unroll
            for (int nt = 0; nt < 4; nt++) {
                int col = colBase + warp_n * 32 + nt * 8 + 2 * tig;
                if (r0 < M)
                    *(__half2*)&g_projh[(long)r0 * NC + col] =
                        __floats2half2_rn(acc[mt][nt][0], acc[mt][nt][1]);
                if (r1 < M)
                    *(__half2*)&g_projh[(long)r1 * NC + col] =
                        __floats2half2_rn(acc[mt][nt][2], acc[mt][nt][3]);
            }
        }
    } else {
        // ---- epilogue: fp32 out = skip projection + bias ----
        #pragma unroll
        for (int mt = 0; mt < 4; mt++) {
            int r0 = rowBase + warp_m * 64 + mt * 16 + gid;
            int r1 = r0 + 8;
            #pragma unroll
            for (int nt = 0; nt < 4; nt++) {
                int col = colBase + warp_n * 32 + nt * 8 + 2 * tig;
                float b0 = bias[col], b1 = bias[col + 1];
                if (r0 < M) {
                    float2 v = make_float2(acc[mt][nt][0] + b0, acc[mt][nt][1] + b1);
                    *(float2*)&out[(long)r0 * NC + col] = v;
                }
                if (r1 < M) {
                    float2 v = make_float2(acc[mt][nt][2] + b0, acc[mt][nt][3] + b1);
                    *(float2*)&out[(long)r1 * NC + col] = v;
                }
            }
        }
    }
}

// ---------------- counting sort: histogram ----------------
__global__ void hist_kernel(const int* __restrict__ etrg) {
    int e = blockIdx.x * blockDim.x + threadIdx.x;
    if (e < EE) atomicAdd(&g_cnt[etrg[e]], 1);
}

// ---------------- scan step 1: per-block exclusive scan + block sums ----------------
__global__ void scan1_kernel() {
    __shared__ int s[256];
    int tid = threadIdx.x;
    int gi = blockIdx.x * 256 + tid;
    int v = (gi < NN) ? g_cnt[gi] : 0;
    s[tid] = v;
    __syncthreads();
    #pragma unroll
    for (int o = 1; o < 256; o <<= 1) {
        int t = (tid >= o) ? s[tid - o] : 0;
        __syncthreads();
        s[tid] += t;
        __syncthreads();
    }
    if (gi < NN) g_off[gi] = s[tid] - v;
    if (tid == 255) g_bsum[blockIdx.x] = s[255];
}

// ---------------- scan steps 2+3 fused ----------------
__global__ void scan23_kernel() {
    __shared__ int s[256];
    int tid = threadIdx.x;
    int v = (tid < NB) ? g_bsum[tid] : 0;
    s[tid] = v;
    __syncthreads();
    #pragma unroll
    for (int o = 1; o < 256; o <<= 1) {
        int t = (tid >= o) ? s[tid - o] : 0;
        __syncthreads();
        s[tid] += t;
        __syncthreads();
    }
    int myoff = (blockIdx.x == 0) ? 0 : s[blockIdx.x - 1];
    int gi = blockIdx.x * 256 + tid;
    if (gi < NN) g_off[gi] += myoff;
}

// ---------------- fused scatter: compute exp(leaky(score)), write sorted ----------------
__global__ void scatter_kernel(const int* __restrict__ esrc, const int* __restrict__ etrg) {
    int e = blockIdx.x * blockDim.x + threadIdx.x;
    if (e >= EE) return;
    int s = esrc[e], t = etrg[e];
    float4 ss = g_ssrc[s];
    float4 st = g_strg[t];
    float4 v;
    v.x = expf(leaky(ss.x + st.x));
    v.y = expf(leaky(ss.y + st.y));
    v.z = expf(leaky(ss.z + st.z));
    v.w = expf(leaky(ss.w + st.w));
    int idx = g_off[t] + atomicAdd(&g_fill[t], 1);
    g_es[idx] = v;
    g_srcs[idx] = s;
}

// ---------------- aggregation: warp per target, SINGLE pass, fp16 gather ----------------
__global__ __launch_bounds__(256) void aggregate_kernel(float* __restrict__ out) {
    int w = (blockIdx.x * blockDim.x + threadIdx.x) >> 5;
    if (w >= NN) return;
    int lane = threadIdx.x & 31;
    int base = g_off[w];
    int deg  = g_cnt[w];
    const int head = lane >> 3;            // 8 cols per lane -> one head

    float dsum = 0.f;                      // this head's softmax denominator
    float2 acc0 = make_float2(0.f, 0.f), acc1 = acc0, acc2 = acc0, acc3 = acc0;
    const __half* ph = g_projh + (long)lane * 8;
    #pragma unroll 2
    for (int i = 0; i < deg; i++) {
        float4 ex = g_es[base + i];        // uniform -> broadcast
        int s = g_srcs[base + i];
        float a = sel4(ex, head);
        dsum += a;
        uint4 h = *(const uint4*)(ph + (long)s * 256);
        float2 f0 = __half22float2(*(__half2*)&h.x);
        float2 f1 = __half22float2(*(__half2*)&h.y);
        float2 f2 = __half22float2(*(__half2*)&h.z);
        float2 f3 = __half22float2(*(__half2*)&h.w);
        acc0.x += f0.x * a; acc0.y += f0.y * a;
        acc1.x += f1.x * a; acc1.y += f1.y * a;
        acc2.x += f2.x * a; acc2.y += f2.y * a;
        acc3.x += f3.x * a; acc3.y += f3.y * a;
    }
    float invh = 1.f / (dsum + 1e-16f);

    float* orow = out + (long)w * 256 + lane * 8;
    float4 v0 = *(float4*)orow;
    float4 v1 = *(float4*)(orow + 4);
    v0.x = leaky(v0.x + acc0.x * invh); v0.y = leaky(v0.y + acc0.y * invh);
    v0.z = leaky(v0.z + acc1.x * invh); v0.w = leaky(v0.w + acc1.y * invh);
    v1.x = leaky(v1.x + acc2.x * invh); v1.y = leaky(v1.y + acc2.y * invh);
    v1.z = leaky(v1.z + acc3.x * invh); v1.w = leaky(v1.w + acc3.y * invh);
    *(float4*)orow       = v0;
    *(float4*)(orow + 4) = v1;
}

// ---------------- launch: fork-join stream DAG (graph-capturable) ----------------
extern "C" void kernel_launch(void* const* d_in, const int* in_sizes, int n_in,
                              void* d_out, int out_size) {
    const float* x      = (const float*)d_in[0];
    const float* W      = (const float*)d_in[1];
    const float* a_src  = (const float*)d_in[2];
    const float* a_trg  = (const float*)d_in[3];
    const float* skip_w = (const float*)d_in[4];
    const float* bias   = (const float*)d_in[5];
    const int*   esrc   = (const int*)d_in[6];
    const int*   etrg   = (const int*)d_in[7];
    float* out = (float*)d_out;

    // one-time infra (created on the uncaptured correctness call; reused under capture)
    static cudaStream_t sSort = nullptr, sScat = nullptr, sGemm = nullptr;
    static cudaEvent_t evFork = nullptr, evSort = nullptr, evConv = nullptr,
                       evZ0 = nullptr, evZ1 = nullptr, evScat = nullptr;
    if (!sSort) {
        cudaStreamCreateWithFlags(&sSort, cudaStreamNonBlocking);
        cudaStreamCreateWithFlags(&sScat, cudaStreamNonBlocking);
        cudaStreamCreateWithFlags(&sGemm, cudaStreamNonBlocking);
        cudaEventCreateWithFlags(&evFork, cudaEventDisableTiming);
        cudaEventCreateWithFlags(&evSort, cudaEventDisableTiming);
        cudaEventCreateWithFlags(&evConv, cudaEventDisableTiming);
        cudaEventCreateWithFlags(&evZ0,   cudaEventDisableTiming);
        cudaEventCreateWithFlags(&evZ1,   cudaEventDisableTiming);
        cudaEventCreateWithFlags(&evScat, cudaEventDisableTiming);
    }

    // ---- fork: sort chain on sSort, concurrent with converts+GEMMs ----
    cudaEventRecord(evFork, 0);
    cudaStreamWaitEvent(sSort, evFork, 0);
    init_sort_kernel<<<(NN + 255) / 256, 256, 0, sSort>>>();
    hist_kernel<<<(EE + 255) / 256, 256, 0, sSort>>>(etrg);
    scan1_kernel<<<NB, 256, 0, sSort>>>();
    scan23_kernel<<<NB, 256, 0, sSort>>>();
    cudaEventRecord(evSort, sSort);

    // ---- main: merged convert, then proj GEMM (z=0, fused scores) ----
    convert_kernel<<<(NN * 32 + 2 * 65536 + 255) / 256, 256>>>(x, W, skip_w);
    cudaEventRecord(evConv, 0);
    dim3 ggrid((NN + 127) / 128, 2);
    gemm_fp16<<<ggrid, 256>>>(out, bias, a_src, a_trg, NN, 0);
    cudaEventRecord(evZ0, 0);

    // ---- skip GEMM (z=1) CONCURRENT with z=0 on sGemm (independent outputs) ----
    cudaStreamWaitEvent(sGemm, evConv, 0);
    gemm_fp16<<<ggrid, 256, 0, sGemm>>>(out, bias, a_src, a_trg, NN, 1);
    cudaEventRecord(evZ1, sGemm);

    // ---- scatter on sScat (needs scores + sort), overlaps z=1 tail ----
    cudaStreamWaitEvent(sScat, evZ0, 0);
    cudaStreamWaitEvent(sScat, evSort, 0);
    scatter_kernel<<<(EE + 255) / 256, 256, 0, sScat>>>(esrc, etrg);
    cudaEventRecord(evScat, sScat);

    // ---- join, then aggregate ----
    cudaStreamWaitEvent(0, evScat, 0);
    cudaStreamWaitEvent(0, evZ1, 0);
    aggregate_kernel<<<(NN * 32 + 255) / 256, 256>>>(out);
}